// round 5
// baseline (speedup 1.0000x reference)
#include <cuda_runtime.h>
#include <math.h>

// Problem constants
#define BB 64
#define SS 512
#define PD 300       // feature dim
#define KK 50        // labels
#define KP 64        // padded labels
#define RR 5
#define NROWS (BB*SS)        // 32768
#define BM 64                // rows per K1 block
#define XSS 302              // xs smem row stride (even, 4*302 % 32 != 0 -> no LDS bank conflict)
#define CH_ELEMS (150*KP*2)  // 19200 pair-packed chat floats

// Scratch (device globals; no runtime allocation allowed)
__device__ __align__(16) float g_chat2[CH_ELEMS];   // [pp=150][k=64][e=2]
__device__ __align__(16) float g_G[NROWS*KK];       // [row][k] cosine scores
__device__ __align__(16) float g_beta[NROWS];       // softmax weights

// ---- packed fp32x2 FMA (Blackwell FFMA2 path) ----
__device__ __forceinline__ void fma2(unsigned long long& d,
                                     unsigned long long a,
                                     unsigned long long b) {
    asm("fma.rn.f32x2 %0, %1, %2, %0;" : "+l"(d) : "l"(a), "l"(b));
}
__device__ __forceinline__ float sum2(unsigned long long v) {
    return __uint_as_float((unsigned)v) + __uint_as_float((unsigned)(v >> 32));
}

// ============================================================
// K0: normalize label embeddings C -> pair-packed g_chat2
//     g_chat2[pp*128 + k*2 + e] = Chat[k][2*pp+e], zero for k>=50
// ============================================================
__global__ void k0_chat(const float* __restrict__ C) {
    __shared__ float inv[KP];
    int tid = threadIdx.x;   // 256
    if (tid < KP) {
        float s = 0.f;
        if (tid < KK) {
            const float* row = C + tid * PD;
            for (int p = 0; p < PD; p++) s = fmaf(row[p], row[p], s);
            inv[tid] = 1.f / (sqrtf(s) + 0.001f);
        } else {
            inv[tid] = 0.f;
        }
    }
    __syncthreads();
    for (int i = tid; i < CH_ELEMS; i += 256) {
        int pp  = i >> 7;        // /128
        int rem = i & 127;
        int k   = rem >> 1;
        int e   = rem & 1;
        int p   = 2 * pp + e;
        float v = 0.f;
        if (k < KK) v = C[k * PD + p] * inv[k];
        g_chat2[i] = v;
    }
}

// ============================================================
// K1: gathered cosine-score GEMM.
// Block: 64 (b,s)-rows x 64 k (50 real). 256 threads, 4x4 tile/thread.
// A = emb[idx[row]] in smem [64][302]; B = g_chat2 in smem (pair-packed).
// Inner loop: fp32x2 packed FMA over 150 p-pairs.
// Norm 1/(||x||+1e-3) folded into epilogue.
// ============================================================
__global__ void __launch_bounds__(256, 1)
k1_scores(const int* __restrict__ idx, const float* __restrict__ emb) {
    extern __shared__ float sm1[];
    float* ch = sm1;                 // CH_ELEMS floats
    float* xs = sm1 + CH_ELEMS;      // BM * XSS floats
    __shared__ float inv[BM];

    const int tid  = threadIdx.x;
    const int lane = tid & 31;
    const int warp = tid >> 5;
    const int row0 = blockIdx.x * BM;

    // stage chat (identical layout, vectorized)
    {
        const float4* src = (const float4*)g_chat2;
        float4* dst = (float4*)ch;
        for (int i = tid; i < CH_ELEMS / 4; i += 256) dst[i] = src[i];
    }
    // gather x rows + compute inverse norms (warp per row)
    for (int r = warp; r < BM; r += 8) {
        const float* src = emb + (size_t)idx[row0 + r] * PD;
        float* xr = xs + r * XSS;
        float ss = 0.f;
        #pragma unroll
        for (int i = 0; i < 10; i++) {
            int p = lane + 32 * i;
            if (p < PD) {
                float v = src[p];
                xr[p] = v;
                ss = fmaf(v, v, ss);
            }
        }
        #pragma unroll
        for (int o = 16; o; o >>= 1) ss += __shfl_xor_sync(0xffffffffu, ss, o);
        if (lane == 0) inv[r] = 1.f / (sqrtf(ss) + 0.001f);
    }
    __syncthreads();

    const int tx = tid & 15;   // k direction (4 k each)
    const int ty = tid >> 4;   // row direction (4 rows each)

    unsigned long long acc[4][4];
    #pragma unroll
    for (int i = 0; i < 4; i++)
        #pragma unroll
        for (int j = 0; j < 4; j++) acc[i][j] = 0ull;

    const float* aBase = xs + (ty * 4) * XSS;
    const float* bBase = ch + tx * 8;

    #pragma unroll 2
    for (int pp = 0; pp < 150; pp++) {
        unsigned long long a0 = *(const unsigned long long*)(aBase + 2 * pp);
        unsigned long long a1 = *(const unsigned long long*)(aBase + XSS + 2 * pp);
        unsigned long long a2 = *(const unsigned long long*)(aBase + 2 * XSS + 2 * pp);
        unsigned long long a3 = *(const unsigned long long*)(aBase + 3 * XSS + 2 * pp);
        ulonglong2 B0 = *(const ulonglong2*)(bBase + pp * 128);      // k0,k1 pairs
        ulonglong2 B1 = *(const ulonglong2*)(bBase + pp * 128 + 4);  // k2,k3 pairs
        fma2(acc[0][0], a0, B0.x); fma2(acc[0][1], a0, B0.y);
        fma2(acc[0][2], a0, B1.x); fma2(acc[0][3], a0, B1.y);
        fma2(acc[1][0], a1, B0.x); fma2(acc[1][1], a1, B0.y);
        fma2(acc[1][2], a1, B1.x); fma2(acc[1][3], a1, B1.y);
        fma2(acc[2][0], a2, B0.x); fma2(acc[2][1], a2, B0.y);
        fma2(acc[2][2], a2, B1.x); fma2(acc[2][3], a2, B1.y);
        fma2(acc[3][0], a3, B0.x); fma2(acc[3][1], a3, B0.y);
        fma2(acc[3][2], a3, B1.x); fma2(acc[3][3], a3, B1.y);
    }

    // epilogue: scale by 1/(||x||+eps), store k<50
    #pragma unroll
    for (int i = 0; i < 4; i++) {
        int row = row0 + ty * 4 + i;
        float iv = inv[ty * 4 + i];
        float* gout = g_G + (size_t)row * KK;
        #pragma unroll
        for (int j = 0; j < 4; j++) {
            int k = tx * 4 + j;
            if (k < KK) gout[k] = sum2(acc[i][j]) * iv;
        }
    }
}

// ============================================================
// K2: per-batch conv(11) + relu + max-over-k + softmax over s.
// One block per b, 512 threads (one per s). G tile in smem with
// 5-row zero padding each side (branch-free conv), stride 51
// (odd -> conflict-free).
// ============================================================
#define GST 51
#define GROWS (SS + 2*RR)   // 522

__global__ void __launch_bounds__(512, 1)
k2_attn(const float* __restrict__ cw, const float* __restrict__ cbp) {
    extern __shared__ float Gs[];   // GROWS * GST
    __shared__ float red1[16], red2[16];
    __shared__ float wloc[11];
    __shared__ float sc[3];         // [0]=conv_b, [1]=max, [2]=sum

    const int b = blockIdx.x, tid = threadIdx.x;
    if (tid < 11) wloc[tid] = cw[tid];
    if (tid == 16) sc[0] = cbp[0];

    // zero the pad rows (indices [0,255] and [517*51, 522*51))
    for (int i = tid; i < RR * GST; i += 512) {
        Gs[i] = 0.f;
        Gs[(SS + RR) * GST + i] = 0.f;
    }
    // load G[b] into padded smem
    const float* Gb = g_G + (size_t)b * SS * KK;
    for (int i = tid; i < SS * KK; i += 512) {
        int s = i / KK, k = i - s * KK;
        Gs[(s + RR) * GST + k] = Gb[i];
    }
    __syncthreads();

    const int s = tid;
    const float cbv = sc[0];
    float m = 0.f;   // relu >= 0, so 0 is a valid identity for the max
    for (int k = 0; k < KK; k++) {
        float v = cbv;
        const float* gp = Gs + s * GST + k;   // = row (s + j - 5 + 5) at j=0
        #pragma unroll
        for (int j = 0; j < 11; j++) v = fmaf(wloc[j], gp[j * GST], v);
        m = fmaxf(m, fmaxf(v, 0.f));
    }

    // block softmax over 512
    const int lane = tid & 31, warp = tid >> 5;
    float mx = m;
    #pragma unroll
    for (int o = 16; o; o >>= 1) mx = fmaxf(mx, __shfl_xor_sync(0xffffffffu, mx, o));
    if (lane == 0) red1[warp] = mx;
    __syncthreads();
    if (warp == 0) {
        float v = (lane < 16) ? red1[lane] : -1e30f;
        #pragma unroll
        for (int o = 8; o; o >>= 1) v = fmaxf(v, __shfl_xor_sync(0xffffffffu, v, o));
        if (lane == 0) sc[1] = v;
    }
    __syncthreads();
    float e = expf(m - sc[1]);
    float sum = e;
    #pragma unroll
    for (int o = 16; o; o >>= 1) sum += __shfl_xor_sync(0xffffffffu, sum, o);
    if (lane == 0) red2[warp] = sum;
    __syncthreads();
    if (warp == 0) {
        float v = (lane < 16) ? red2[lane] : 0.f;
        #pragma unroll
        for (int o = 8; o; o >>= 1) v += __shfl_xor_sync(0xffffffffu, v, o);
        if (lane == 0) sc[2] = v;
    }
    __syncthreads();
    g_beta[b * SS + s] = e / sc[2];
}

// ============================================================
// K3: per-batch beta-weighted pooling (re-gather emb, L2-hot)
//     then out = pooled @ W2^T + b2.
// One block per b, 320 threads.
// ============================================================
__global__ void __launch_bounds__(320, 1)
k3_out(const int* __restrict__ idx, const float* __restrict__ emb,
       const float* __restrict__ W2, const float* __restrict__ b2,
       float* __restrict__ out) {
    __shared__ float sbeta[SS];
    __shared__ int   sidx[SS];
    __shared__ float pooled[PD];

    const int b = blockIdx.x, tid = threadIdx.x;
    for (int i = tid; i < SS; i += 320) {
        sbeta[i] = g_beta[b * SS + i];
        sidx[i]  = idx[b * SS + i];
    }
    __syncthreads();

    if (tid < PD) {
        float a0 = 0.f, a1 = 0.f, a2 = 0.f, a3 = 0.f;
        for (int s = 0; s < SS; s += 4) {
            a0 = fmaf(sbeta[s],     emb[(size_t)sidx[s]     * PD + tid], a0);
            a1 = fmaf(sbeta[s + 1], emb[(size_t)sidx[s + 1] * PD + tid], a1);
            a2 = fmaf(sbeta[s + 2], emb[(size_t)sidx[s + 2] * PD + tid], a2);
            a3 = fmaf(sbeta[s + 3], emb[(size_t)sidx[s + 3] * PD + tid], a3);
        }
        pooled[tid] = ((a0 + a1) + (a2 + a3)) * (1.0f / (float)SS);
    }
    __syncthreads();

    const int warp = tid >> 5, lane = tid & 31;  // 10 warps x 5 k
    #pragma unroll
    for (int kk = 0; kk < 5; kk++) {
        int k = warp * 5 + kk;
        float d = 0.f;
        for (int p = lane; p < PD; p += 32) d = fmaf(pooled[p], W2[k * PD + p], d);
        #pragma unroll
        for (int o = 16; o; o >>= 1) d += __shfl_xor_sync(0xffffffffu, d, o);
        if (lane == 0) out[b * KK + k] = d + b2[k];
    }
}

// ============================================================
extern "C" void kernel_launch(void* const* d_in, const int* in_sizes, int n_in,
                              void* d_out, int out_size) {
    const int*   idx    = (const int*)d_in[0];
    const float* emb    = (const float*)d_in[1];
    const float* C      = (const float*)d_in[2];
    const float* conv_w = (const float*)d_in[3];
    const float* conv_b = (const float*)d_in[4];
    const float* W2     = (const float*)d_in[5];
    const float* b2     = (const float*)d_in[6];
    float*       out    = (float*)d_out;

    const int sm1 = (CH_ELEMS + BM * XSS) * (int)sizeof(float);   // ~154 KB
    const int sm2 = GROWS * GST * (int)sizeof(float);             // ~106 KB
    cudaFuncSetAttribute(k1_scores, cudaFuncAttributeMaxDynamicSharedMemorySize, sm1);
    cudaFuncSetAttribute(k2_attn,   cudaFuncAttributeMaxDynamicSharedMemorySize, sm2);

    k0_chat<<<1, 256>>>(C);
    k1_scores<<<NROWS / BM, 256, sm1>>>(idx, emb);
    k2_attn<<<BB, 512, sm2>>>(conv_w, conv_b);
    k3_out<<<BB, 320>>>(idx, emb, W2, b2, out);
}

// round 6
// speedup vs baseline: 1.3667x; 1.3667x over previous
#include <cuda_runtime.h>
#include <math.h>

// Problem constants
#define BB 64
#define SS 512
#define PD 300       // feature dim
#define KK 50        // labels
#define KP 64        // padded labels
#define RR 5
#define NROWS (BB*SS)        // 32768
#define BM 64                // rows per K1 block
#define XSS 304              // xs smem row stride (multiple of 4 -> 16B-aligned rows for cp.async)
#define CH_ELEMS (150*KP*2)  // 19200 pair-packed chat floats

// Scratch (device globals; no runtime allocation allowed)
__device__ __align__(16) float g_chat2[CH_ELEMS];   // [pp=150][half=2][tx=16][q=4] packed (see k0)
__device__ __align__(16) float g_G[NROWS*KK];       // [row][k] cosine scores
__device__ __align__(16) float g_beta[NROWS];       // softmax weights
__device__ __align__(16) float g_part[BB*8*PD];     // pooling partials [b][chunk][p]

// ---- packed fp32x2 FMA (Blackwell FFMA2 path) ----
__device__ __forceinline__ void fma2(unsigned long long& d,
                                     unsigned long long a,
                                     unsigned long long b) {
    asm("fma.rn.f32x2 %0, %1, %2, %0;" : "+l"(d) : "l"(a), "l"(b));
}
__device__ __forceinline__ float sum2(unsigned long long v) {
    return __uint_as_float((unsigned)v) + __uint_as_float((unsigned)(v >> 32));
}
__device__ __forceinline__ unsigned s2u(const void* p) {
    unsigned a;
    asm("{ .reg .u64 t; cvta.to.shared.u64 t, %1; cvt.u32.u64 %0, t; }"
        : "=r"(a) : "l"(p));
    return a;
}

// ============================================================
// K0: normalize label embeddings C -> conflict-free packed g_chat2.
// Layout per pp (one 512B row): [half=0: tx=0..15 x {k=4tx pair, k=4tx+1 pair}]
//                               [half=1: tx=0..15 x {k=4tx+2 pair, k=4tx+3 pair}]
// So thread tx reads its 4 k-pairs as two LDS.128 at tx*16B stride
// (16 lanes x 16B contiguous = bank-conflict-free).
// ============================================================
__global__ void k0_chat(const float* __restrict__ C) {
    __shared__ float inv[KP];
    int tid = threadIdx.x;   // 256
    if (tid < KP) {
        float s = 0.f;
        if (tid < KK) {
            const float* row = C + tid * PD;
            for (int p = 0; p < PD; p++) s = fmaf(row[p], row[p], s);
            inv[tid] = 1.f / (sqrtf(s) + 0.001f);
        } else {
            inv[tid] = 0.f;
        }
    }
    __syncthreads();
    for (int i = tid; i < CH_ELEMS; i += 256) {
        int pp   = i >> 7;       // /128
        int rem  = i & 127;
        int half = rem >> 6;
        int w    = rem & 63;
        int tx   = w >> 2;
        int q    = w & 3;
        int k    = 4 * tx + 2 * half + (q >> 1);
        int e    = q & 1;
        int p    = 2 * pp + e;
        float v = 0.f;
        if (k < KK) v = C[k * PD + p] * inv[k];
        g_chat2[i] = v;
    }
}

// ============================================================
// K1: gathered cosine-score GEMM.
// Block: 64 (b,s)-rows x 64 k (50 real). 256 threads, 4x4 tile/thread.
// Gather + chat staging via cp.async (batched latency).
// Inner loop: fp32x2 packed FMA over 150 p-pairs, conflict-free B loads.
// ============================================================
__global__ void __launch_bounds__(256, 1)
k1_scores(const int* __restrict__ idx, const float* __restrict__ emb) {
    extern __shared__ float sm1[];
    float* ch = sm1;                 // CH_ELEMS floats
    float* xs = sm1 + CH_ELEMS;      // BM * XSS floats
    __shared__ float inv[BM];

    const int tid  = threadIdx.x;
    const int lane = tid & 31;
    const int warp = tid >> 5;
    const int row0 = blockIdx.x * BM;

    // stage chat via cp.async (16B)
    {
        const float4* src = (const float4*)g_chat2;
        unsigned dst = s2u(ch);
        for (int i = tid; i < CH_ELEMS / 4; i += 256)
            asm volatile("cp.async.cg.shared.global [%0], [%1], 16;"
                         :: "r"(dst + 16u * (unsigned)i), "l"(src + i));
    }
    // gather x rows via cp.async (all 8 rows per warp issued before waiting)
    for (int r = warp; r < BM; r += 8) {
        const float4* src = (const float4*)(emb + (size_t)idx[row0 + r] * PD);
        unsigned dst = s2u(xs + r * XSS);
        #pragma unroll
        for (int i = 0; i < 3; i++) {
            int p4 = lane + 32 * i;
            if (p4 < 75)  // 300 floats = 75 float4
                asm volatile("cp.async.cg.shared.global [%0], [%1], 16;"
                             :: "r"(dst + 16u * (unsigned)p4), "l"(src + p4));
        }
    }
    asm volatile("cp.async.commit_group;");
    asm volatile("cp.async.wait_group 0;" ::: "memory");
    __syncthreads();

    // inverse norms from smem (warp per row)
    for (int r = warp; r < BM; r += 8) {
        const float* xr = xs + r * XSS;
        float ss = 0.f;
        #pragma unroll
        for (int i = 0; i < 10; i++) {
            int p = lane + 32 * i;
            if (p < PD) { float v = xr[p]; ss = fmaf(v, v, ss); }
        }
        #pragma unroll
        for (int o = 16; o; o >>= 1) ss += __shfl_xor_sync(0xffffffffu, ss, o);
        if (lane == 0) inv[r] = 1.f / (sqrtf(ss) + 0.001f);
    }
    __syncthreads();

    const int tx = tid & 15;   // k direction (4 k each)
    const int ty = tid >> 4;   // row direction (4 rows each)

    unsigned long long acc[4][4];
    #pragma unroll
    for (int i = 0; i < 4; i++)
        #pragma unroll
        for (int j = 0; j < 4; j++) acc[i][j] = 0ull;

    const float* aBase = xs + (ty * 4) * XSS;
    const float* bBase = ch + tx * 4;   // 16B-stride chunks, conflict-free

    #pragma unroll 2
    for (int pp = 0; pp < 150; pp++) {
        unsigned long long a0 = *(const unsigned long long*)(aBase + 2 * pp);
        unsigned long long a1 = *(const unsigned long long*)(aBase + XSS + 2 * pp);
        unsigned long long a2 = *(const unsigned long long*)(aBase + 2 * XSS + 2 * pp);
        unsigned long long a3 = *(const unsigned long long*)(aBase + 3 * XSS + 2 * pp);
        ulonglong2 B0 = *(const ulonglong2*)(bBase + pp * 128);       // k=4tx, 4tx+1
        ulonglong2 B1 = *(const ulonglong2*)(bBase + pp * 128 + 64);  // k=4tx+2, 4tx+3
        fma2(acc[0][0], a0, B0.x); fma2(acc[0][1], a0, B0.y);
        fma2(acc[0][2], a0, B1.x); fma2(acc[0][3], a0, B1.y);
        fma2(acc[1][0], a1, B0.x); fma2(acc[1][1], a1, B0.y);
        fma2(acc[1][2], a1, B1.x); fma2(acc[1][3], a1, B1.y);
        fma2(acc[2][0], a2, B0.x); fma2(acc[2][1], a2, B0.y);
        fma2(acc[2][2], a2, B1.x); fma2(acc[2][3], a2, B1.y);
        fma2(acc[3][0], a3, B0.x); fma2(acc[3][1], a3, B0.y);
        fma2(acc[3][2], a3, B1.x); fma2(acc[3][3], a3, B1.y);
    }

    // epilogue: scale by 1/(||x||+eps), store k<50
    #pragma unroll
    for (int i = 0; i < 4; i++) {
        int row = row0 + ty * 4 + i;
        float iv = inv[ty * 4 + i];
        float* gout = g_G + (size_t)row * KK;
        #pragma unroll
        for (int j = 0; j < 4; j++) {
            int k = tx * 4 + j;
            if (k < KK) gout[k] = sum2(acc[i][j]) * iv;
        }
    }
}

// ============================================================
// K2: per-batch conv(11) + relu + max-over-k + softmax over s.
// ============================================================
#define GST 51
#define GROWS (SS + 2*RR)   // 522

__global__ void __launch_bounds__(512, 1)
k2_attn(const float* __restrict__ cw, const float* __restrict__ cbp) {
    extern __shared__ float Gs[];   // GROWS * GST
    __shared__ float red1[16], red2[16];
    __shared__ float wloc[11];
    __shared__ float sc[3];         // [0]=conv_b, [1]=max, [2]=sum

    const int b = blockIdx.x, tid = threadIdx.x;
    if (tid < 11) wloc[tid] = cw[tid];
    if (tid == 16) sc[0] = cbp[0];

    for (int i = tid; i < RR * GST; i += 512) {
        Gs[i] = 0.f;
        Gs[(SS + RR) * GST + i] = 0.f;
    }
    const float* Gb = g_G + (size_t)b * SS * KK;
    for (int i = tid; i < SS * KK; i += 512) {
        int s = i / KK, k = i - s * KK;
        Gs[(s + RR) * GST + k] = Gb[i];
    }
    __syncthreads();

    const int s = tid;
    const float cbv = sc[0];
    float m = 0.f;   // relu >= 0
    for (int k = 0; k < KK; k++) {
        float v = cbv;
        const float* gp = Gs + s * GST + k;
        #pragma unroll
        for (int j = 0; j < 11; j++) v = fmaf(wloc[j], gp[j * GST], v);
        m = fmaxf(m, fmaxf(v, 0.f));
    }

    const int lane = tid & 31, warp = tid >> 5;
    float mx = m;
    #pragma unroll
    for (int o = 16; o; o >>= 1) mx = fmaxf(mx, __shfl_xor_sync(0xffffffffu, mx, o));
    if (lane == 0) red1[warp] = mx;
    __syncthreads();
    if (warp == 0) {
        float v = (lane < 16) ? red1[lane] : -1e30f;
        #pragma unroll
        for (int o = 8; o; o >>= 1) v = fmaxf(v, __shfl_xor_sync(0xffffffffu, v, o));
        if (lane == 0) sc[1] = v;
    }
    __syncthreads();
    float e = expf(m - sc[1]);
    float sum = e;
    #pragma unroll
    for (int o = 16; o; o >>= 1) sum += __shfl_xor_sync(0xffffffffu, sum, o);
    if (lane == 0) red2[warp] = sum;
    __syncthreads();
    if (warp == 0) {
        float v = (lane < 16) ? red2[lane] : 0.f;
        #pragma unroll
        for (int o = 8; o; o >>= 1) v += __shfl_xor_sync(0xffffffffu, v, o);
        if (lane == 0) sc[2] = v;
    }
    __syncthreads();
    g_beta[b * SS + s] = e / sc[2];
}

// ============================================================
// K3a: parallel pooling partials. grid (8 chunks, 64 b), 320 threads.
// Each block reduces 64 s-positions into g_part[b][chunk][p].
// ============================================================
__global__ void __launch_bounds__(320, 1)
k3a_pool(const int* __restrict__ idx, const float* __restrict__ emb) {
    __shared__ float sbeta[64];
    __shared__ int   sidx[64];
    const int cx = blockIdx.x, b = blockIdx.y, tid = threadIdx.x;
    const int s0 = b * SS + cx * 64;
    if (tid < 64) {
        sbeta[tid] = g_beta[s0 + tid];
        sidx[tid]  = idx[s0 + tid];
    }
    __syncthreads();
    if (tid < PD) {
        float a0 = 0.f, a1 = 0.f, a2 = 0.f, a3 = 0.f;
        #pragma unroll 4
        for (int s = 0; s < 64; s += 4) {
            a0 = fmaf(sbeta[s],     emb[(size_t)sidx[s]     * PD + tid], a0);
            a1 = fmaf(sbeta[s + 1], emb[(size_t)sidx[s + 1] * PD + tid], a1);
            a2 = fmaf(sbeta[s + 2], emb[(size_t)sidx[s + 2] * PD + tid], a2);
            a3 = fmaf(sbeta[s + 3], emb[(size_t)sidx[s + 3] * PD + tid], a3);
        }
        g_part[(b * 8 + cx) * PD + tid] = (a0 + a1) + (a2 + a3);
    }
}

// ============================================================
// K3b: combine partials + final GEMV out = pooled @ W2^T + b2.
// ============================================================
__global__ void __launch_bounds__(320, 1)
k3b_out(const float* __restrict__ W2, const float* __restrict__ b2,
        float* __restrict__ out) {
    __shared__ float pooled[PD];
    const int b = blockIdx.x, tid = threadIdx.x;
    if (tid < PD) {
        float s = 0.f;
        #pragma unroll
        for (int c = 0; c < 8; c++) s += g_part[(b * 8 + c) * PD + tid];
        pooled[tid] = s * (1.0f / (float)SS);
    }
    __syncthreads();

    const int warp = tid >> 5, lane = tid & 31;  // 10 warps x 5 k
    #pragma unroll
    for (int kk = 0; kk < 5; kk++) {
        int k = warp * 5 + kk;
        float d = 0.f;
        for (int p = lane; p < PD; p += 32) d = fmaf(pooled[p], W2[k * PD + p], d);
        #pragma unroll
        for (int o = 16; o; o >>= 1) d += __shfl_xor_sync(0xffffffffu, d, o);
        if (lane == 0) out[b * KK + k] = d + b2[k];
    }
}

// ============================================================
extern "C" void kernel_launch(void* const* d_in, const int* in_sizes, int n_in,
                              void* d_out, int out_size) {
    const int*   idx    = (const int*)d_in[0];
    const float* emb    = (const float*)d_in[1];
    const float* C      = (const float*)d_in[2];
    const float* conv_w = (const float*)d_in[3];
    const float* conv_b = (const float*)d_in[4];
    const float* W2     = (const float*)d_in[5];
    const float* b2     = (const float*)d_in[6];
    float*       out    = (float*)d_out;

    const int sm1 = (CH_ELEMS + BM * XSS) * (int)sizeof(float);   // ~151 KB
    const int sm2 = GROWS * GST * (int)sizeof(float);             // ~106 KB
    cudaFuncSetAttribute(k1_scores, cudaFuncAttributeMaxDynamicSharedMemorySize, sm1);
    cudaFuncSetAttribute(k2_attn,   cudaFuncAttributeMaxDynamicSharedMemorySize, sm2);

    k0_chat<<<1, 256>>>(C);
    k1_scores<<<NROWS / BM, 256, sm1>>>(idx, emb);
    k2_attn<<<BB, 512, sm2>>>(conv_w, conv_b);
    k3a_pool<<<dim3(8, BB), 320>>>(idx, emb);
    k3b_out<<<BB, 320>>>(W2, b2, out);
}